// round 8
// baseline (speedup 1.0000x reference)
#include <cuda_runtime.h>
#include <cuda_fp16.h>
#include <mma.h>
#include <math.h>

using namespace nvcuda;

#define NN 100000
#define EE 1600000
#define SCAN_B 512
#define NB ((NN + SCAN_B - 1) / SCAN_B)

struct __align__(8) Edge { int s; float w; };

// ---------------- scratch (alloc-free: __device__ globals) ----------------
__device__ int    g_is64;
__device__ int    g_deg[NN];
__device__ int    g_cnt[NN];
__device__ int    g_off[NN];
__device__ int    g_cur[NN];
__device__ int    g_bsum[NB];
__device__ int    g_bpre[NB];
__device__ float  g_dinv[NN];
__device__ float  g_selfw[NN];
__device__ Edge   g_csr[EE];
__device__ __half g_bufT[(size_t)(NN + 128) * 128];  // GEMM out (row-padded for tile stores)
__device__ __half g_bufOh[(size_t)NN * 128];         // activations (gather out)

// ---------------- detect dtype + init degrees ----------------
__global__ void k_pre0(const void* __restrict__ ei) {
    int i = blockIdx.x * blockDim.x + threadIdx.x;
    if (i < NN) g_deg[i] = 1;  // self-loop
    if (i == 0) {
        const int* w = (const int*)ei;
        int nz = 0;
        for (int k = 1; k < 256; k += 2) nz += (w[k] != 0);
        g_is64 = (nz == 0) ? 1 : 0;
    }
}

__device__ __forceinline__ int edge_at(const void* __restrict__ ei, long long i) {
    if (g_is64) return (int)((const long long*)ei)[i];
    return ((const int*)ei)[i];
}

__global__ void k_count_deg(const void* __restrict__ ei) {
    int i = blockIdx.x * blockDim.x + threadIdx.x;
    if (i < EE) atomicAdd(&g_deg[edge_at(ei, (long long)EE + i)], 1);
}

// ---------------- dinv/selfw/cnt fused with local scan ----------------
__global__ void k_dinv_scan() {
    __shared__ int sm[SCAN_B];
    int v = blockIdx.x * SCAN_B + threadIdx.x;
    int c = 0;
    if (v < NN) {
        int dg = g_deg[v];
        float dv = rsqrtf((float)dg);
        g_dinv[v] = dv;
        g_selfw[v] = dv * dv;
        c = dg - 1;
        g_cnt[v] = c;
    }
    sm[threadIdx.x] = c;
    __syncthreads();
    for (int off = 1; off < SCAN_B; off <<= 1) {
        int y = (threadIdx.x >= off) ? sm[threadIdx.x - off] : 0;
        __syncthreads();
        sm[threadIdx.x] += y;
        __syncthreads();
    }
    if (v < NN) g_off[v] = sm[threadIdx.x] - c;
    if (threadIdx.x == SCAN_B - 1) g_bsum[blockIdx.x] = sm[SCAN_B - 1];
}

__global__ void k_scan_bsum() {
    if (threadIdx.x == 0 && blockIdx.x == 0) {
        int run = 0;
        for (int i = 0; i < NB; i++) { g_bpre[i] = run; run += g_bsum[i]; }
    }
}

__global__ void k_scan_add() {
    int v = blockIdx.x * blockDim.x + threadIdx.x;
    if (v < NN) {
        g_off[v] += g_bpre[v / SCAN_B];
        g_cur[v] = 0;
    }
}

// ---------------- tensor-core GEMM body (device fn) ----------------
// 128 rows x O cols per block, single K shot. fp32 accumulate, direct half
// fragment store to gmem (out buffer row-padded to a multiple of 128).
template <int K, int O, bool IN_HALF>
__device__ __forceinline__ void gemm_body(const void* __restrict__ Xv,
                                          const float* __restrict__ W,
                                          __half* __restrict__ out, int n,
                                          int bx, char* smraw) {
    constexpr int LDA = K + 8;
    constexpr int LDB = O + 8;
    constexpr int NT = O / 16;
    __half* Xs = (__half*)smraw;                 // 128 x LDA
    __half* Ws = ((__half*)smraw) + 128 * LDA;   // K x LDB

    int tid = threadIdx.x;
    int warp = tid >> 5;
    int row0 = bx * 128;

    for (int i = tid * 8; i < 128 * K; i += 256 * 8) {
        int r = i / K, c = i % K;
        uint4 pk = make_uint4(0u, 0u, 0u, 0u);
        if (row0 + r < n) {
            if constexpr (IN_HALF) {
                pk = *(const uint4*)&((const __half*)Xv)[(size_t)(row0 + r) * K + c];
            } else {
                const float* Xf = (const float*)Xv;
                float4 a = *(const float4*)&Xf[(size_t)(row0 + r) * K + c];
                float4 b = *(const float4*)&Xf[(size_t)(row0 + r) * K + c + 4];
                __half2* h = (__half2*)&pk;
                h[0] = __floats2half2_rn(a.x, a.y);
                h[1] = __floats2half2_rn(a.z, a.w);
                h[2] = __floats2half2_rn(b.x, b.y);
                h[3] = __floats2half2_rn(b.z, b.w);
            }
        }
        *(uint4*)&Xs[r * LDA + c] = pk;
    }
    for (int i = tid * 4; i < K * O; i += 256 * 4) {
        int k = i / O, c = i % O;
        float4 wv = *(const float4*)&W[(size_t)k * O + c];
        uint2 pk;
        ((__half2*)&pk)[0] = __floats2half2_rn(wv.x, wv.y);
        ((__half2*)&pk)[1] = __floats2half2_rn(wv.z, wv.w);
        *(uint2*)&Ws[k * LDB + c] = pk;
    }
    __syncthreads();

    wmma::fragment<wmma::accumulator, 16, 16, 16, float> acc[NT];
#pragma unroll
    for (int t = 0; t < NT; t++) wmma::fill_fragment(acc[t], 0.0f);

#pragma unroll
    for (int k0 = 0; k0 < K; k0 += 16) {
        wmma::fragment<wmma::matrix_a, 16, 16, 16, __half, wmma::row_major> a;
        wmma::load_matrix_sync(a, &Xs[warp * 16 * LDA + k0], LDA);
#pragma unroll
        for (int t = 0; t < NT; t++) {
            wmma::fragment<wmma::matrix_b, 16, 16, 16, __half, wmma::row_major> b;
            wmma::load_matrix_sync(b, &Ws[k0 * LDB + t * 16], LDB);
            wmma::mma_sync(acc[t], a, b, acc[t]);
        }
    }

    // convert fp32 acc -> half fragment, store straight to gmem
#pragma unroll
    for (int t = 0; t < NT; t++) {
        wmma::fragment<wmma::accumulator, 16, 16, 16, __half> h;
#pragma unroll
        for (int e2 = 0; e2 < h.num_elements; e2++) h.x[e2] = __float2half(acc[t].x[e2]);
        wmma::store_matrix_sync(&out[(size_t)(row0 + warp * 16) * O + t * 16], h, O,
                                wmma::mem_row_major);
    }
}

// ---------------- fused layer-1 GEMM + CSR scatter ----------------
__global__ __launch_bounds__(256, 3) void k_gemm1_csr(const float* __restrict__ X,
                                                      const float* __restrict__ W1,
                                                      __half* __restrict__ out, int n,
                                                      const void* __restrict__ ei, int gb) {
    extern __shared__ char smraw[];
    if ((int)blockIdx.x < gb) {
        gemm_body<128, 128, false>(X, W1, out, n, blockIdx.x, smraw);
    } else {
        int e = (blockIdx.x - gb) * 256 + threadIdx.x;
        if (e < EE) {
            int s = edge_at(ei, e);
            int d = edge_at(ei, (long long)EE + e);
            Edge ed;
            ed.s = s;
            ed.w = g_dinv[s] * g_dinv[d];
            int pos = g_off[d] + atomicAdd(&g_cur[d], 1);
            g_csr[pos] = ed;
        }
    }
}

// ---------------- standalone GEMM (layers 2, 3) ----------------
template <int K, int O, bool IN_HALF>
__global__ __launch_bounds__(256) void wgemm_kernel(const void* __restrict__ Xv,
                                                    const float* __restrict__ W,
                                                    __half* __restrict__ out, int n) {
    extern __shared__ char smraw[];
    gemm_body<K, O, IN_HALF>(Xv, W, out, n, blockIdx.x, smraw);
}

// ---------------- CSR gather (fp16 in, fp32 acc, fp16 out) ----------------
template <int F>
__global__ void gather_kernel(const float* __restrict__ bias, __half* __restrict__ O, int n) {
    constexpr int G = F / 8;
    int t = blockIdx.x * blockDim.x + threadIdx.x;
    int v = t / G;
    int q = t % G;
    if (v >= n) return;
    const __half* T = g_bufT;
    size_t fo = (size_t)q * 8;

    float acc[8];
    {
        float sw = g_selfw[v];
        uint4 r = *(const uint4*)&T[(size_t)v * F + fo];
        const __half2* h = (const __half2*)&r;
#pragma unroll
        for (int p = 0; p < 4; p++) {
            float2 f = __half22float2(h[p]);
            acc[2 * p] = sw * f.x;
            acc[2 * p + 1] = sw * f.y;
        }
    }

    int beg = g_off[v];
    int cnt = g_cnt[v];
#pragma unroll 4
    for (int i = 0; i < cnt; i++) {
        Edge e = g_csr[beg + i];
        uint4 r = *(const uint4*)&T[(size_t)e.s * F + fo];
        const __half2* h = (const __half2*)&r;
#pragma unroll
        for (int p = 0; p < 4; p++) {
            float2 f = __half22float2(h[p]);
            acc[2 * p] += e.w * f.x;
            acc[2 * p + 1] += e.w * f.y;
        }
    }

    float4 b0 = *(const float4*)&bias[fo];
    float4 b1 = *(const float4*)&bias[fo + 4];
    uint4 pk;
    ((__half2*)&pk)[0] = __floats2half2_rn(fmaxf(acc[0] + b0.x, 0.f), fmaxf(acc[1] + b0.y, 0.f));
    ((__half2*)&pk)[1] = __floats2half2_rn(fmaxf(acc[2] + b0.z, 0.f), fmaxf(acc[3] + b0.w, 0.f));
    ((__half2*)&pk)[2] = __floats2half2_rn(fmaxf(acc[4] + b1.x, 0.f), fmaxf(acc[5] + b1.y, 0.f));
    ((__half2*)&pk)[3] = __floats2half2_rn(fmaxf(acc[6] + b1.z, 0.f), fmaxf(acc[7] + b1.w, 0.f));
    *(uint4*)&O[(size_t)v * F + fo] = pk;
}

// ---------------- layer-3 gather fused with logistic head ----------------
__global__ void gather_head_kernel(const float* __restrict__ bias,
                                   const float* __restrict__ Wl,
                                   const float* __restrict__ bl,
                                   float* __restrict__ out, int n) {
    constexpr int F = 32, G = 4;
    int t = blockIdx.x * blockDim.x + threadIdx.x;
    int v = t / G;
    int q = t % G;
    if (v >= n) return;
    const __half* T = g_bufT;
    size_t fo = (size_t)q * 8;

    float acc[8];
    {
        float sw = g_selfw[v];
        uint4 r = *(const uint4*)&T[(size_t)v * F + fo];
        const __half2* h = (const __half2*)&r;
#pragma unroll
        for (int p = 0; p < 4; p++) {
            float2 f = __half22float2(h[p]);
            acc[2 * p] = sw * f.x;
            acc[2 * p + 1] = sw * f.y;
        }
    }

    int beg = g_off[v];
    int cnt = g_cnt[v];
#pragma unroll 4
    for (int i = 0; i < cnt; i++) {
        Edge e = g_csr[beg + i];
        uint4 r = *(const uint4*)&T[(size_t)e.s * F + fo];
        const __half2* h = (const __half2*)&r;
#pragma unroll
        for (int p = 0; p < 4; p++) {
            float2 f = __half22float2(h[p]);
            acc[2 * p] += e.w * f.x;
            acc[2 * p + 1] += e.w * f.y;
        }
    }

    float4 b0 = *(const float4*)&bias[fo];
    float4 b1 = *(const float4*)&bias[fo + 4];
    float4 w0 = *(const float4*)&Wl[fo];
    float4 w1 = *(const float4*)&Wl[fo + 4];
    float p = fmaxf(acc[0] + b0.x, 0.f) * w0.x + fmaxf(acc[1] + b0.y, 0.f) * w0.y +
              fmaxf(acc[2] + b0.z, 0.f) * w0.z + fmaxf(acc[3] + b0.w, 0.f) * w0.w +
              fmaxf(acc[4] + b1.x, 0.f) * w1.x + fmaxf(acc[5] + b1.y, 0.f) * w1.y +
              fmaxf(acc[6] + b1.z, 0.f) * w1.z + fmaxf(acc[7] + b1.w, 0.f) * w1.w;
#pragma unroll
    for (int off = 2; off; off >>= 1) p += __shfl_down_sync(0xffffffffu, p, off, G);
    if (q == 0) out[v] = 1.f / (1.f + __expf(-(p + bl[0])));
}

extern "C" void kernel_launch(void* const* d_in, const int* in_sizes, int n_in,
                              void* d_out, int out_size) {
    const float* x = (const float*)d_in[0];
    const void* ei = (const void*)d_in[1];
    const float* W1 = (const float*)d_in[2];
    const float* b1 = (const float*)d_in[3];
    const float* W2 = (const float*)d_in[4];
    const float* b2 = (const float*)d_in[5];
    const float* W3 = (const float*)d_in[6];
    const float* b3 = (const float*)d_in[7];
    const float* Wl = (const float*)d_in[8];
    const float* bl = (const float*)d_in[9];
    float* out = (float*)d_out;
    int n = NN;

    constexpr int SM1 = (128 * (128 + 8) + 128 * (128 + 8)) * 2;  // 69632
    constexpr int SM2 = (128 * (128 + 8) + 128 * (64 + 8)) * 2;   // 53248
    constexpr int SM3 = (128 * (64 + 8) + 64 * (32 + 8)) * 2;     // 23552
    cudaFuncSetAttribute(k_gemm1_csr, cudaFuncAttributeMaxDynamicSharedMemorySize, SM1);
    cudaFuncSetAttribute(wgemm_kernel<128, 64, true>, cudaFuncAttributeMaxDynamicSharedMemorySize, SM2);
    cudaFuncSetAttribute(wgemm_kernel<64, 32, true>, cudaFuncAttributeMaxDynamicSharedMemorySize, SM3);

    __half* T;
    __half* Oh;
    cudaGetSymbolAddress((void**)&T, g_bufT);
    cudaGetSymbolAddress((void**)&Oh, g_bufOh);

    // preprocessing
    k_pre0<<<(NN + 255) / 256, 256>>>(ei);
    k_count_deg<<<(EE + 255) / 256, 256>>>(ei);
    k_dinv_scan<<<NB, SCAN_B>>>();
    k_scan_bsum<<<1, 32>>>();
    k_scan_add<<<(NN + 255) / 256, 256>>>();

    // --- layer 1 GEMM (tensor cores) overlapped with CSR scatter ---
    int gb = (n + 127) / 128;                 // 782 gemm blocks
    int cb = (EE + 255) / 256;                // 6250 csr blocks
    k_gemm1_csr<<<gb + cb, 256, SM1>>>(x, W1, T, n, ei, gb);

    // --- layer 1 gather ---
    gather_kernel<128><<<(n * 16 + 255) / 256, 256>>>(b1, Oh, n);

    // --- layer 2: 128 -> 64 ---
    wgemm_kernel<128, 64, true><<<(n + 127) / 128, 256, SM2>>>(Oh, W2, T, n);
    gather_kernel<64><<<(n * 8 + 255) / 256, 256>>>(b2, Oh, n);

    // --- layer 3: 64 -> 32 + head ---
    wgemm_kernel<64, 32, true><<<(n + 127) / 128, 256, SM3>>>(Oh, W3, T, n);
    gather_head_kernel<<<(n * 4 + 255) / 256, 256>>>(b3, Wl, bl, out, n);
}

// round 9
// speedup vs baseline: 1.2487x; 1.2487x over previous
#include <cuda_runtime.h>
#include <cuda_fp16.h>
#include <mma.h>
#include <math.h>

using namespace nvcuda;

#define NN 100000
#define EE 1600000
#define SCAN_B 512
#define NB ((NN + SCAN_B - 1) / SCAN_B)

struct __align__(8) Edge { int s; float w; };

// ---------------- scratch (alloc-free: __device__ globals) ----------------
__device__ int    g_is64;
__device__ int    g_deg[NN];
__device__ int    g_cnt[NN];
__device__ int    g_off[NN];
__device__ int    g_cur[NN];
__device__ int    g_bsum[NB];
__device__ int    g_bpre[NB];
__device__ float  g_dinv[NN];
__device__ float  g_selfw[NN];
__device__ Edge   g_csr[EE];
__device__ __half g_bufT[(size_t)(NN + 128) * 128];  // GEMM out (row-padded for tile stores)
__device__ __half g_bufOh[(size_t)NN * 128];         // activations (gather out)

// ---------------- detect dtype + init degrees ----------------
__global__ void k_pre0(const void* __restrict__ ei) {
    int i = blockIdx.x * blockDim.x + threadIdx.x;
    if (i < NN) g_deg[i] = 1;  // self-loop
    if (i == 0) {
        const int* w = (const int*)ei;
        int nz = 0;
        for (int k = 1; k < 256; k += 2) nz += (w[k] != 0);
        g_is64 = (nz == 0) ? 1 : 0;
    }
}

__device__ __forceinline__ int edge_at(const void* __restrict__ ei, long long i) {
    if (g_is64) return (int)((const long long*)ei)[i];
    return ((const int*)ei)[i];
}

__global__ void k_count_deg(const void* __restrict__ ei) {
    int i = blockIdx.x * blockDim.x + threadIdx.x;
    if (i < EE) atomicAdd(&g_deg[edge_at(ei, (long long)EE + i)], 1);
}

// ---------------- dinv/selfw/cnt fused with local scan ----------------
__global__ void k_dinv_scan() {
    __shared__ int sm[SCAN_B];
    int v = blockIdx.x * SCAN_B + threadIdx.x;
    int c = 0;
    if (v < NN) {
        int dg = g_deg[v];
        float dv = rsqrtf((float)dg);
        g_dinv[v] = dv;
        g_selfw[v] = dv * dv;
        c = dg - 1;
        g_cnt[v] = c;
    }
    sm[threadIdx.x] = c;
    __syncthreads();
    for (int off = 1; off < SCAN_B; off <<= 1) {
        int y = (threadIdx.x >= off) ? sm[threadIdx.x - off] : 0;
        __syncthreads();
        sm[threadIdx.x] += y;
        __syncthreads();
    }
    if (v < NN) g_off[v] = sm[threadIdx.x] - c;
    if (threadIdx.x == SCAN_B - 1) g_bsum[blockIdx.x] = sm[SCAN_B - 1];
}

// parallel scan over the NB block sums (NB=196 <= 256)
__global__ void k_scan_bsum_par() {
    __shared__ int sm[256];
    int i = threadIdx.x;
    int v = (i < NB) ? g_bsum[i] : 0;
    sm[i] = v;
    __syncthreads();
    for (int off = 1; off < 256; off <<= 1) {
        int y = (i >= off) ? sm[i - off] : 0;
        __syncthreads();
        sm[i] += y;
        __syncthreads();
    }
    if (i < NB) g_bpre[i] = sm[i] - v;  // exclusive prefix
}

__global__ void k_scan_add() {
    int v = blockIdx.x * blockDim.x + threadIdx.x;
    if (v < NN) {
        g_off[v] += g_bpre[v / SCAN_B];
        g_cur[v] = 0;
    }
}

__global__ void k_build_csr(const void* __restrict__ ei) {
    int e = blockIdx.x * blockDim.x + threadIdx.x;
    if (e >= EE) return;
    int s = edge_at(ei, e);
    int d = edge_at(ei, (long long)EE + e);
    Edge ed;
    ed.s = s;
    ed.w = g_dinv[s] * g_dinv[d];
    int pos = g_off[d] + atomicAdd(&g_cur[d], 1);
    g_csr[pos] = ed;
}

// ---------------- tensor-core GEMM: 128 rows x O cols per block -------------
// fp32 accumulate, direct half fragment store (out row-padded to 128).
template <int K, int O, bool IN_HALF>
__global__ __launch_bounds__(256) void wgemm_kernel(const void* __restrict__ Xv,
                                                    const float* __restrict__ W,
                                                    __half* __restrict__ out, int n) {
    constexpr int LDA = K + 8;
    constexpr int LDB = O + 8;
    constexpr int NT = O / 16;
    extern __shared__ char smraw[];
    __half* Xs = (__half*)smraw;                 // 128 x LDA
    __half* Ws = ((__half*)smraw) + 128 * LDA;   // K x LDB

    int tid = threadIdx.x;
    int warp = tid >> 5;
    int row0 = blockIdx.x * 128;

    for (int i = tid * 8; i < 128 * K; i += 256 * 8) {
        int r = i / K, c = i % K;
        uint4 pk = make_uint4(0u, 0u, 0u, 0u);
        if (row0 + r < n) {
            if constexpr (IN_HALF) {
                pk = *(const uint4*)&((const __half*)Xv)[(size_t)(row0 + r) * K + c];
            } else {
                const float* Xf = (const float*)Xv;
                float4 a = *(const float4*)&Xf[(size_t)(row0 + r) * K + c];
                float4 b = *(const float4*)&Xf[(size_t)(row0 + r) * K + c + 4];
                __half2* h = (__half2*)&pk;
                h[0] = __floats2half2_rn(a.x, a.y);
                h[1] = __floats2half2_rn(a.z, a.w);
                h[2] = __floats2half2_rn(b.x, b.y);
                h[3] = __floats2half2_rn(b.z, b.w);
            }
        }
        *(uint4*)&Xs[r * LDA + c] = pk;
    }
    for (int i = tid * 4; i < K * O; i += 256 * 4) {
        int k = i / O, c = i % O;
        float4 wv = *(const float4*)&W[(size_t)k * O + c];
        uint2 pk;
        ((__half2*)&pk)[0] = __floats2half2_rn(wv.x, wv.y);
        ((__half2*)&pk)[1] = __floats2half2_rn(wv.z, wv.w);
        *(uint2*)&Ws[k * LDB + c] = pk;
    }
    __syncthreads();

    wmma::fragment<wmma::accumulator, 16, 16, 16, float> acc[NT];
#pragma unroll
    for (int t = 0; t < NT; t++) wmma::fill_fragment(acc[t], 0.0f);

#pragma unroll
    for (int k0 = 0; k0 < K; k0 += 16) {
        wmma::fragment<wmma::matrix_a, 16, 16, 16, __half, wmma::row_major> a;
        wmma::load_matrix_sync(a, &Xs[warp * 16 * LDA + k0], LDA);
#pragma unroll
        for (int t = 0; t < NT; t++) {
            wmma::fragment<wmma::matrix_b, 16, 16, 16, __half, wmma::row_major> b;
            wmma::load_matrix_sync(b, &Ws[k0 * LDB + t * 16], LDB);
            wmma::mma_sync(acc[t], a, b, acc[t]);
        }
    }

#pragma unroll
    for (int t = 0; t < NT; t++) {
        wmma::fragment<wmma::accumulator, 16, 16, 16, __half> h;
#pragma unroll
        for (int e2 = 0; e2 < h.num_elements; e2++) h.x[e2] = __float2half(acc[t].x[e2]);
        wmma::store_matrix_sync(&out[(size_t)(row0 + warp * 16) * O + t * 16], h, O,
                                wmma::mem_row_major);
    }
}

// ---------------- CSR gather (fp16 in, fp32 acc, fp16 out) ----------------
template <int F>
__global__ void gather_kernel(const float* __restrict__ bias, __half* __restrict__ O, int n) {
    constexpr int G = F / 8;
    int t = blockIdx.x * blockDim.x + threadIdx.x;
    int v = t / G;
    int q = t % G;
    if (v >= n) return;
    const __half* T = g_bufT;
    size_t fo = (size_t)q * 8;

    float acc[8];
    {
        float sw = g_selfw[v];
        uint4 r = *(const uint4*)&T[(size_t)v * F + fo];
        const __half2* h = (const __half2*)&r;
#pragma unroll
        for (int p = 0; p < 4; p++) {
            float2 f = __half22float2(h[p]);
            acc[2 * p] = sw * f.x;
            acc[2 * p + 1] = sw * f.y;
        }
    }

    int beg = g_off[v];
    int cnt = g_cnt[v];
#pragma unroll 4
    for (int i = 0; i < cnt; i++) {
        Edge e = g_csr[beg + i];
        uint4 r = *(const uint4*)&T[(size_t)e.s * F + fo];
        const __half2* h = (const __half2*)&r;
#pragma unroll
        for (int p = 0; p < 4; p++) {
            float2 f = __half22float2(h[p]);
            acc[2 * p] += e.w * f.x;
            acc[2 * p + 1] += e.w * f.y;
        }
    }

    float4 b0 = *(const float4*)&bias[fo];
    float4 b1 = *(const float4*)&bias[fo + 4];
    uint4 pk;
    ((__half2*)&pk)[0] = __floats2half2_rn(fmaxf(acc[0] + b0.x, 0.f), fmaxf(acc[1] + b0.y, 0.f));
    ((__half2*)&pk)[1] = __floats2half2_rn(fmaxf(acc[2] + b0.z, 0.f), fmaxf(acc[3] + b0.w, 0.f));
    ((__half2*)&pk)[2] = __floats2half2_rn(fmaxf(acc[4] + b1.x, 0.f), fmaxf(acc[5] + b1.y, 0.f));
    ((__half2*)&pk)[3] = __floats2half2_rn(fmaxf(acc[6] + b1.z, 0.f), fmaxf(acc[7] + b1.w, 0.f));
    *(uint4*)&O[(size_t)v * F + fo] = pk;
}

// ---------------- layer-3 gather fused with logistic head ----------------
__global__ void gather_head_kernel(const float* __restrict__ bias,
                                   const float* __restrict__ Wl,
                                   const float* __restrict__ bl,
                                   float* __restrict__ out, int n) {
    constexpr int F = 32, G = 4;
    int t = blockIdx.x * blockDim.x + threadIdx.x;
    int v = t / G;
    int q = t % G;
    if (v >= n) return;
    const __half* T = g_bufT;
    size_t fo = (size_t)q * 8;

    float acc[8];
    {
        float sw = g_selfw[v];
        uint4 r = *(const uint4*)&T[(size_t)v * F + fo];
        const __half2* h = (const __half2*)&r;
#pragma unroll
        for (int p = 0; p < 4; p++) {
            float2 f = __half22float2(h[p]);
            acc[2 * p] = sw * f.x;
            acc[2 * p + 1] = sw * f.y;
        }
    }

    int beg = g_off[v];
    int cnt = g_cnt[v];
#pragma unroll 4
    for (int i = 0; i < cnt; i++) {
        Edge e = g_csr[beg + i];
        uint4 r = *(const uint4*)&T[(size_t)e.s * F + fo];
        const __half2* h = (const __half2*)&r;
#pragma unroll
        for (int p = 0; p < 4; p++) {
            float2 f = __half22float2(h[p]);
            acc[2 * p] += e.w * f.x;
            acc[2 * p + 1] += e.w * f.y;
        }
    }

    float4 b0 = *(const float4*)&bias[fo];
    float4 b1 = *(const float4*)&bias[fo + 4];
    float4 w0 = *(const float4*)&Wl[fo];
    float4 w1 = *(const float4*)&Wl[fo + 4];
    float p = fmaxf(acc[0] + b0.x, 0.f) * w0.x + fmaxf(acc[1] + b0.y, 0.f) * w0.y +
              fmaxf(acc[2] + b0.z, 0.f) * w0.z + fmaxf(acc[3] + b0.w, 0.f) * w0.w +
              fmaxf(acc[4] + b1.x, 0.f) * w1.x + fmaxf(acc[5] + b1.y, 0.f) * w1.y +
              fmaxf(acc[6] + b1.z, 0.f) * w1.z + fmaxf(acc[7] + b1.w, 0.f) * w1.w;
#pragma unroll
    for (int off = 2; off; off >>= 1) p += __shfl_down_sync(0xffffffffu, p, off, G);
    if (q == 0) out[v] = 1.f / (1.f + __expf(-(p + bl[0])));
}

extern "C" void kernel_launch(void* const* d_in, const int* in_sizes, int n_in,
                              void* d_out, int out_size) {
    const float* x = (const float*)d_in[0];
    const void* ei = (const void*)d_in[1];
    const float* W1 = (const float*)d_in[2];
    const float* b1 = (const float*)d_in[3];
    const float* W2 = (const float*)d_in[4];
    const float* b2 = (const float*)d_in[5];
    const float* W3 = (const float*)d_in[6];
    const float* b3 = (const float*)d_in[7];
    const float* Wl = (const float*)d_in[8];
    const float* bl = (const float*)d_in[9];
    float* out = (float*)d_out;
    int n = NN;

    constexpr int SM1 = (128 * (128 + 8) + 128 * (128 + 8)) * 2;  // 69632
    constexpr int SM2 = (128 * (128 + 8) + 128 * (64 + 8)) * 2;   // 53248
    constexpr int SM3 = (128 * (64 + 8) + 64 * (32 + 8)) * 2;     // 23552
    cudaFuncSetAttribute(wgemm_kernel<128, 128, false>, cudaFuncAttributeMaxDynamicSharedMemorySize, SM1);
    cudaFuncSetAttribute(wgemm_kernel<128, 64, true>, cudaFuncAttributeMaxDynamicSharedMemorySize, SM2);
    cudaFuncSetAttribute(wgemm_kernel<64, 32, true>, cudaFuncAttributeMaxDynamicSharedMemorySize, SM3);

    __half* T;
    __half* Oh;
    cudaGetSymbolAddress((void**)&T, g_bufT);
    cudaGetSymbolAddress((void**)&Oh, g_bufOh);

    // one-time host objects (no device memory)
    static cudaStream_t s2 = nullptr;
    static cudaEvent_t evFork = nullptr, evJoin = nullptr;
    if (s2 == nullptr) {
        cudaStreamCreateWithFlags(&s2, cudaStreamNonBlocking);
        cudaEventCreateWithFlags(&evFork, cudaEventDisableTiming);
        cudaEventCreateWithFlags(&evJoin, cudaEventDisableTiming);
    }

    // ---- fork: layer-1 GEMM on s2 (depends only on x, W1) ----
    cudaEventRecord(evFork, 0);
    cudaStreamWaitEvent(s2, evFork, 0);
    wgemm_kernel<128, 128, false><<<(n + 127) / 128, 256, SM1, s2>>>(x, W1, T, n);
    cudaEventRecord(evJoin, s2);

    // ---- preprocessing chain on the capture stream ----
    k_pre0<<<(NN + 255) / 256, 256>>>(ei);
    k_count_deg<<<(EE + 255) / 256, 256>>>(ei);
    k_dinv_scan<<<NB, SCAN_B>>>();
    k_scan_bsum_par<<<1, 256>>>();
    k_scan_add<<<(NN + 255) / 256, 256>>>();
    k_build_csr<<<(EE + 255) / 256, 256>>>(ei);

    // ---- join: gather1 needs both gemm1 (T) and the CSR ----
    cudaStreamWaitEvent(0, evJoin, 0);
    gather_kernel<128><<<(n * 16 + 255) / 256, 256>>>(b1, Oh, n);

    // --- layer 2: 128 -> 64 ---
    wgemm_kernel<128, 64, true><<<(n + 127) / 128, 256, SM2>>>(Oh, W2, T, n);
    gather_kernel<64><<<(n * 8 + 255) / 256, 256>>>(b2, Oh, n);

    // --- layer 3: 64 -> 32 + head ---
    wgemm_kernel<64, 32, true><<<(n + 127) / 128, 256, SM3>>>(Oh, W3, T, n);
    gather_head_kernel<<<(n * 4 + 255) / 256, 256>>>(b3, Wl, bl, out, n);
}

// round 10
// speedup vs baseline: 1.2717x; 1.0183x over previous
#include <cuda_runtime.h>
#include <cuda_fp16.h>
#include <mma.h>
#include <math.h>

using namespace nvcuda;

#define NN 100000
#define EE 1600000
#define SCAN_B 512
#define NB ((NN + SCAN_B - 1) / SCAN_B)

struct __align__(8) Edge { int s; float w; };

// ---------------- scratch (alloc-free: __device__ globals) ----------------
__device__ int    g_is64;
__device__ int    g_deg[NN];
__device__ int    g_cnt[NN];
__device__ int    g_off[NN];
__device__ int    g_cur[NN];
__device__ int    g_bsum[NB];
__device__ int    g_bpre[NB];
__device__ float  g_dinv[NN];
__device__ float  g_selfw[NN];
__device__ Edge   g_csr[EE];
__device__ __half g_bufT[(size_t)(NN + 128) * 128];  // GEMM out (row-padded for tile stores)
__device__ __half g_bufOh[(size_t)NN * 128];         // activations (gather out)

// ---------------- detect dtype + init degrees ----------------
__global__ void k_pre0(const void* __restrict__ ei) {
    int i = blockIdx.x * blockDim.x + threadIdx.x;
    if (i < NN) g_deg[i] = 1;  // self-loop
    if (i == 0) {
        const int* w = (const int*)ei;
        int nz = 0;
        for (int k = 1; k < 256; k += 2) nz += (w[k] != 0);
        g_is64 = (nz == 0) ? 1 : 0;
    }
}

__device__ __forceinline__ int edge_at(const void* __restrict__ ei, long long i) {
    if (g_is64) return (int)((const long long*)ei)[i];
    return ((const int*)ei)[i];
}

__global__ void k_count_deg(const void* __restrict__ ei) {
    int i = blockIdx.x * blockDim.x + threadIdx.x;
    if (i < EE) atomicAdd(&g_deg[edge_at(ei, (long long)EE + i)], 1);
}

// ---------------- dinv/selfw/cnt fused with local scan ----------------
__global__ void k_dinv_scan() {
    __shared__ int sm[SCAN_B];
    int v = blockIdx.x * SCAN_B + threadIdx.x;
    int c = 0;
    if (v < NN) {
        int dg = g_deg[v];
        float dv = rsqrtf((float)dg);
        g_dinv[v] = dv;
        g_selfw[v] = dv * dv;
        c = dg - 1;
        g_cnt[v] = c;
    }
    sm[threadIdx.x] = c;
    __syncthreads();
    for (int off = 1; off < SCAN_B; off <<= 1) {
        int y = (threadIdx.x >= off) ? sm[threadIdx.x - off] : 0;
        __syncthreads();
        sm[threadIdx.x] += y;
        __syncthreads();
    }
    if (v < NN) g_off[v] = sm[threadIdx.x] - c;
    if (threadIdx.x == SCAN_B - 1) g_bsum[blockIdx.x] = sm[SCAN_B - 1];
}

// parallel scan over the NB block sums (NB=196 <= 256)
__global__ void k_scan_bsum_par() {
    __shared__ int sm[256];
    int i = threadIdx.x;
    int v = (i < NB) ? g_bsum[i] : 0;
    sm[i] = v;
    __syncthreads();
    for (int off = 1; off < 256; off <<= 1) {
        int y = (i >= off) ? sm[i - off] : 0;
        __syncthreads();
        sm[i] += y;
        __syncthreads();
    }
    if (i < NB) g_bpre[i] = sm[i] - v;  // exclusive prefix
}

__global__ void k_scan_add() {
    int v = blockIdx.x * blockDim.x + threadIdx.x;
    if (v < NN) {
        g_off[v] += g_bpre[v / SCAN_B];
        g_cur[v] = 0;
    }
}

__global__ void k_build_csr(const void* __restrict__ ei) {
    int e = blockIdx.x * blockDim.x + threadIdx.x;
    if (e >= EE) return;
    int s = edge_at(ei, e);
    int d = edge_at(ei, (long long)EE + e);
    Edge ed;
    ed.s = s;
    ed.w = g_dinv[s] * g_dinv[d];
    int pos = g_off[d] + atomicAdd(&g_cur[d], 1);
    g_csr[pos] = ed;
}

// ---------------- tensor-core GEMM: 512 threads, 128 rows x O cols ---------
// 16 warps: warp = 16-row strip (w>>1) x O/2 col half (w&1). fp32 accumulate,
// direct half fragment store (out row-padded to 128 rows).
template <int K, int O, bool IN_HALF>
__global__ __launch_bounds__(512) void wgemm_kernel(const void* __restrict__ Xv,
                                                    const float* __restrict__ W,
                                                    __half* __restrict__ out, int n) {
    constexpr int LDA = K + 8;
    constexpr int LDB = O + 8;
    constexpr int NT = O / 32;           // 16-col tiles per warp (half of O)
    extern __shared__ char smraw[];
    __half* Xs = (__half*)smraw;                 // 128 x LDA
    __half* Ws = ((__half*)smraw) + 128 * LDA;   // K x LDB

    int tid = threadIdx.x;
    int warp = tid >> 5;
    int rstrip = warp >> 1;              // 0..7
    int chalf = warp & 1;                // 0..1
    int row0 = blockIdx.x * 128;

    for (int i = tid * 8; i < 128 * K; i += 512 * 8) {
        int r = i / K, c = i % K;
        uint4 pk = make_uint4(0u, 0u, 0u, 0u);
        if (row0 + r < n) {
            if constexpr (IN_HALF) {
                pk = *(const uint4*)&((const __half*)Xv)[(size_t)(row0 + r) * K + c];
            } else {
                const float* Xf = (const float*)Xv;
                float4 a = *(const float4*)&Xf[(size_t)(row0 + r) * K + c];
                float4 b = *(const float4*)&Xf[(size_t)(row0 + r) * K + c + 4];
                __half2* h = (__half2*)&pk;
                h[0] = __floats2half2_rn(a.x, a.y);
                h[1] = __floats2half2_rn(a.z, a.w);
                h[2] = __floats2half2_rn(b.x, b.y);
                h[3] = __floats2half2_rn(b.z, b.w);
            }
        }
        *(uint4*)&Xs[r * LDA + c] = pk;
    }
    for (int i = tid * 4; i < K * O; i += 512 * 4) {
        int k = i / O, c = i % O;
        float4 wv = *(const float4*)&W[(size_t)k * O + c];
        uint2 pk;
        ((__half2*)&pk)[0] = __floats2half2_rn(wv.x, wv.y);
        ((__half2*)&pk)[1] = __floats2half2_rn(wv.z, wv.w);
        *(uint2*)&Ws[k * LDB + c] = pk;
    }
    __syncthreads();

    wmma::fragment<wmma::accumulator, 16, 16, 16, float> acc[NT];
#pragma unroll
    for (int t = 0; t < NT; t++) wmma::fill_fragment(acc[t], 0.0f);

#pragma unroll
    for (int k0 = 0; k0 < K; k0 += 16) {
        wmma::fragment<wmma::matrix_a, 16, 16, 16, __half, wmma::row_major> a;
        wmma::load_matrix_sync(a, &Xs[rstrip * 16 * LDA + k0], LDA);
#pragma unroll
        for (int t = 0; t < NT; t++) {
            wmma::fragment<wmma::matrix_b, 16, 16, 16, __half, wmma::row_major> b;
            wmma::load_matrix_sync(b, &Ws[k0 * LDB + chalf * (O / 2) + t * 16], LDB);
            wmma::mma_sync(acc[t], a, b, acc[t]);
        }
    }

#pragma unroll
    for (int t = 0; t < NT; t++) {
        wmma::fragment<wmma::accumulator, 16, 16, 16, __half> h;
#pragma unroll
        for (int e2 = 0; e2 < h.num_elements; e2++) h.x[e2] = __float2half(acc[t].x[e2]);
        wmma::store_matrix_sync(&out[(size_t)(row0 + rstrip * 16) * O + chalf * (O / 2) + t * 16],
                                h, O, wmma::mem_row_major);
    }
}

// ---------------- CSR gather (fp16 in, fp32 acc, fp16 out) ----------------
template <int F>
__global__ void gather_kernel(const float* __restrict__ bias, __half* __restrict__ O, int n) {
    constexpr int G = F / 8;
    int t = blockIdx.x * blockDim.x + threadIdx.x;
    int v = t / G;
    int q = t % G;
    if (v >= n) return;
    const __half* T = g_bufT;
    size_t fo = (size_t)q * 8;

    float acc[8];
    {
        float sw = g_selfw[v];
        uint4 r = *(const uint4*)&T[(size_t)v * F + fo];
        const __half2* h = (const __half2*)&r;
#pragma unroll
        for (int p = 0; p < 4; p++) {
            float2 f = __half22float2(h[p]);
            acc[2 * p] = sw * f.x;
            acc[2 * p + 1] = sw * f.y;
        }
    }

    int beg = g_off[v];
    int cnt = g_cnt[v];
#pragma unroll 4
    for (int i = 0; i < cnt; i++) {
        Edge e = g_csr[beg + i];
        uint4 r = *(const uint4*)&T[(size_t)e.s * F + fo];
        const __half2* h = (const __half2*)&r;
#pragma unroll
        for (int p = 0; p < 4; p++) {
            float2 f = __half22float2(h[p]);
            acc[2 * p] += e.w * f.x;
            acc[2 * p + 1] += e.w * f.y;
        }
    }

    float4 b0 = *(const float4*)&bias[fo];
    float4 b1 = *(const float4*)&bias[fo + 4];
    uint4 pk;
    ((__half2*)&pk)[0] = __floats2half2_rn(fmaxf(acc[0] + b0.x, 0.f), fmaxf(acc[1] + b0.y, 0.f));
    ((__half2*)&pk)[1] = __floats2half2_rn(fmaxf(acc[2] + b0.z, 0.f), fmaxf(acc[3] + b0.w, 0.f));
    ((__half2*)&pk)[2] = __floats2half2_rn(fmaxf(acc[4] + b1.x, 0.f), fmaxf(acc[5] + b1.y, 0.f));
    ((__half2*)&pk)[3] = __floats2half2_rn(fmaxf(acc[6] + b1.z, 0.f), fmaxf(acc[7] + b1.w, 0.f));
    *(uint4*)&O[(size_t)v * F + fo] = pk;
}

// ---------------- layer-3 gather fused with logistic head ----------------
__global__ void gather_head_kernel(const float* __restrict__ bias,
                                   const float* __restrict__ Wl,
                                   const float* __restrict__ bl,
                                   float* __restrict__ out, int n) {
    constexpr int F = 32, G = 4;
    int t = blockIdx.x * blockDim.x + threadIdx.x;
    int v = t / G;
    int q = t % G;
    if (v >= n) return;
    const __half* T = g_bufT;
    size_t fo = (size_t)q * 8;

    float acc[8];
    {
        float sw = g_selfw[v];
        uint4 r = *(const uint4*)&T[(size_t)v * F + fo];
        const __half2* h = (const __half2*)&r;
#pragma unroll
        for (int p = 0; p < 4; p++) {
            float2 f = __half22float2(h[p]);
            acc[2 * p] = sw * f.x;
            acc[2 * p + 1] = sw * f.y;
        }
    }

    int beg = g_off[v];
    int cnt = g_cnt[v];
#pragma unroll 4
    for (int i = 0; i < cnt; i++) {
        Edge e = g_csr[beg + i];
        uint4 r = *(const uint4*)&T[(size_t)e.s * F + fo];
        const __half2* h = (const __half2*)&r;
#pragma unroll
        for (int p = 0; p < 4; p++) {
            float2 f = __half22float2(h[p]);
            acc[2 * p] += e.w * f.x;
            acc[2 * p + 1] += e.w * f.y;
        }
    }

    float4 b0 = *(const float4*)&bias[fo];
    float4 b1 = *(const float4*)&bias[fo + 4];
    float4 w0 = *(const float4*)&Wl[fo];
    float4 w1 = *(const float4*)&Wl[fo + 4];
    float p = fmaxf(acc[0] + b0.x, 0.f) * w0.x + fmaxf(acc[1] + b0.y, 0.f) * w0.y +
              fmaxf(acc[2] + b0.z, 0.f) * w0.z + fmaxf(acc[3] + b0.w, 0.f) * w0.w +
              fmaxf(acc[4] + b1.x, 0.f) * w1.x + fmaxf(acc[5] + b1.y, 0.f) * w1.y +
              fmaxf(acc[6] + b1.z, 0.f) * w1.z + fmaxf(acc[7] + b1.w, 0.f) * w1.w;
#pragma unroll
    for (int off = 2; off; off >>= 1) p += __shfl_down_sync(0xffffffffu, p, off, G);
    if (q == 0) out[v] = 1.f / (1.f + __expf(-(p + bl[0])));
}

extern "C" void kernel_launch(void* const* d_in, const int* in_sizes, int n_in,
                              void* d_out, int out_size) {
    const float* x = (const float*)d_in[0];
    const void* ei = (const void*)d_in[1];
    const float* W1 = (const float*)d_in[2];
    const float* b1 = (const float*)d_in[3];
    const float* W2 = (const float*)d_in[4];
    const float* b2 = (const float*)d_in[5];
    const float* W3 = (const float*)d_in[6];
    const float* b3 = (const float*)d_in[7];
    const float* Wl = (const float*)d_in[8];
    const float* bl = (const float*)d_in[9];
    float* out = (float*)d_out;
    int n = NN;

    constexpr int SM1 = (128 * (128 + 8) + 128 * (128 + 8)) * 2;  // 69632
    constexpr int SM2 = (128 * (128 + 8) + 128 * (64 + 8)) * 2;   // 53248
    constexpr int SM3 = (128 * (64 + 8) + 64 * (32 + 8)) * 2;     // 23552
    cudaFuncSetAttribute(wgemm_kernel<128, 128, false>, cudaFuncAttributeMaxDynamicSharedMemorySize, SM1);
    cudaFuncSetAttribute(wgemm_kernel<128, 64, true>, cudaFuncAttributeMaxDynamicSharedMemorySize, SM2);
    cudaFuncSetAttribute(wgemm_kernel<64, 32, true>, cudaFuncAttributeMaxDynamicSharedMemorySize, SM3);

    __half* T;
    __half* Oh;
    cudaGetSymbolAddress((void**)&T, g_bufT);
    cudaGetSymbolAddress((void**)&Oh, g_bufOh);

    // one-time host objects (no device memory)
    static cudaStream_t s2 = nullptr;
    static cudaEvent_t evFork = nullptr, evJoin = nullptr;
    if (s2 == nullptr) {
        cudaStreamCreateWithFlags(&s2, cudaStreamNonBlocking);
        cudaEventCreateWithFlags(&evFork, cudaEventDisableTiming);
        cudaEventCreateWithFlags(&evJoin, cudaEventDisableTiming);
    }

    // ---- fork: layer-1 GEMM on s2 (depends only on x, W1) ----
    cudaEventRecord(evFork, 0);
    cudaStreamWaitEvent(s2, evFork, 0);
    wgemm_kernel<128, 128, false><<<(n + 127) / 128, 512, SM1, s2>>>(x, W1, T, n);
    cudaEventRecord(evJoin, s2);

    // ---- preprocessing chain on the capture stream ----
    k_pre0<<<(NN + 255) / 256, 256>>>(ei);
    k_count_deg<<<(EE + 255) / 256, 256>>>(ei);
    k_dinv_scan<<<NB, SCAN_B>>>();
    k_scan_bsum_par<<<1, 256>>>();
    k_scan_add<<<(NN + 255) / 256, 256>>>();
    k_build_csr<<<(EE + 255) / 256, 256>>>(ei);

    // ---- join: gather1 needs both gemm1 (T) and the CSR ----
    cudaStreamWaitEvent(0, evJoin, 0);
    gather_kernel<128><<<(n * 16 + 255) / 256, 256>>>(b1, Oh, n);

    // --- layer 2: 128 -> 64 ---
    wgemm_kernel<128, 64, true><<<(n + 127) / 128, 512, SM2>>>(Oh, W2, T, n);
    gather_kernel<64><<<(n * 8 + 255) / 256, 256>>>(b2, Oh, n);

    // --- layer 3: 64 -> 32 + head ---
    wgemm_kernel<64, 32, true><<<(n + 127) / 128, 512, SM3>>>(Oh, W3, T, n);
    gather_head_kernel<<<(n * 4 + 255) / 256, 256>>>(b3, Wl, bl, out, n);
}